// round 13
// baseline (speedup 1.0000x reference)
#include <cuda_runtime.h>
#include <cuda_fp16.h>
#include <cstdint>

#define S_LEN 8192
#define HD 64
#define NHEADS 8
#define WW 512
#define QB 128
#define NQB (S_LEN/QB)            /* 64 */
#define UNITS 8192                /* 64 qb x 128 key-tiles */
#define ATTN_GRID 296             /* 2 CTAs per SM */
#define NSLOT 8
#define CEXP 0.1803368801111204f  /* 0.125 * log2(e) */

static __device__ float g_Opart[NSLOT][S_LEN * HD];   // zero-init; unused slots stay 0
static __device__ float g_lpart[NSLOT][S_LEN];
static __device__ __align__(16) __half g_qh[S_LEN * HD];
static __device__ __align__(16) __half g_kh[S_LEN * HD];
static __device__ __align__(16) __half g_vh[S_LEN * HD];
static __device__ __align__(16) __half g_wht[WW * HD];   // W_sum^T fp16 [n][k]

// ---------------- helpers ----------------
__device__ __forceinline__ uint32_t smem_u32(const void* p) {
    uint32_t a;
    asm("{ .reg .u64 t; cvta.to.shared.u64 t, %1; cvt.u32.u64 %0, t; }" : "=r"(a) : "l"(p));
    return a;
}
__device__ __forceinline__ void ldsm4(uint32_t* r, uint32_t a) {
    asm volatile("ldmatrix.sync.aligned.m8n8.x4.shared.b16 {%0,%1,%2,%3}, [%4];"
                 : "=r"(r[0]), "=r"(r[1]), "=r"(r[2]), "=r"(r[3]) : "r"(a));
}
__device__ __forceinline__ void ldsm4t(uint32_t* r, uint32_t a) {
    asm volatile("ldmatrix.sync.aligned.m8n8.x4.trans.shared.b16 {%0,%1,%2,%3}, [%4];"
                 : "=r"(r[0]), "=r"(r[1]), "=r"(r[2]), "=r"(r[3]) : "r"(a));
}
__device__ __forceinline__ void mma16816(float* d, const uint32_t* a, uint32_t b0, uint32_t b1) {
    asm volatile(
        "mma.sync.aligned.m16n8k16.row.col.f32.f16.f16.f32 "
        "{%0,%1,%2,%3}, {%4,%5,%6,%7}, {%8,%9}, {%0,%1,%2,%3};"
        : "+f"(d[0]), "+f"(d[1]), "+f"(d[2]), "+f"(d[3])
        : "r"(a[0]), "r"(a[1]), "r"(a[2]), "r"(a[3]), "r"(b0), "r"(b1));
}
__device__ __forceinline__ uint32_t hpack(float a, float b) {
    __half2 h = __floats2half2_rn(a, b);
    return *reinterpret_cast<uint32_t*>(&h);
}
__device__ __forceinline__ void packpair(float a, float b, uint32_t& hi, uint32_t& lo) {
    __half2 h = __floats2half2_rn(a, b);
    hi = *reinterpret_cast<uint32_t*>(&h);
    float fa = __half2float(h.x);
    float fb = __half2float(h.y);
    lo = hpack(a - fa, b - fb);
}
__device__ __forceinline__ float ex2f(float x) {
    float y; asm("ex2.approx.f32 %0, %1;" : "=f"(y) : "f"(x)); return y;
}
#define CP_ASYNC16(dst, src) \
    asm volatile("cp.async.cg.shared.global [%0], [%1], 16;" :: "r"(dst), "l"(src))
#define CP_COMMIT() asm volatile("cp.async.commit_group;" ::: "memory")
#define CP_WAIT(n)  asm volatile("cp.async.wait_group %0;" :: "n"(n) : "memory")

// first CTA whose range contains unit u  ( = ceil((u+1)*G/U) - 1 )
__device__ __forceinline__ int cta_of_unit(int u) {
    return (u * ATTN_GRID + ATTN_GRID - 1) / UNITS;
}

// ---------------------------------------------------------------------------
// Kernel 0 (merged prologue): blocks 0..767 convert one tensor each
// (8 elems/thread, uint4 stores); blocks 768..895 reduce w_o.
// ---------------------------------------------------------------------------
__global__ void prologue_kernel(const float* __restrict__ q, const float* __restrict__ k,
                                const float* __restrict__ v, const float* __restrict__ w_o) {
    const int b = blockIdx.x;
    if (b < 768) {
        const int a = b >> 8;                               // tensor 0..2
        const int t = ((b & 255) << 8) + threadIdx.x;       // 0..65535
        const int off = t * 8;
        const float* srcs[3] = {q, k, v};
        __half* dsts[3] = {g_qh, g_kh, g_vh};
        const float4* s = reinterpret_cast<const float4*>(srcs[a] + off);
        float4 x0 = s[0], x1 = s[1];
        reinterpret_cast<uint4*>(dsts[a] + off)[0] =
            make_uint4(hpack(x0.x, x0.y), hpack(x0.z, x0.w),
                       hpack(x1.x, x1.y), hpack(x1.z, x1.w));
    } else {
        int idx = (b - 768) * blockDim.x + threadIdx.x;     // 0..32767
        int d = idx >> 9;
        int c = idx & 511;
        float s = 0.f;
#pragma unroll
        for (int h = 0; h < NHEADS; ++h)
            s += w_o[(h * HD + d) * WW + c];
        g_wht[c * HD + d] = __float2half(s);
    }
}

// ---------------------------------------------------------------------------
// Kernel 1: persistent flash attention over flat (qb, ktile) units.
// 296 CTAs (2/SM) x 256 threads. cp.async triple-buffered KH/VH.
// Smem: Q@0 (16KB); buf b @ 16384 + b*16384: KH@0 VH@8192. Total 64KB.
// ---------------------------------------------------------------------------
__device__ __forceinline__ void issue_tile(uint32_t bufBase, int keyRow0, int tid) {
    const int key = tid >> 2, sub = tid & 3;
    const size_t gOff = (size_t)(keyRow0 + key) * HD;
#pragma unroll
    for (int i = 0; i < 2; ++i) {
        const int ch = sub * 2 + i;
        const uint32_t swo = ((ch ^ (key & 7)) << 4);
        CP_ASYNC16(bufBase + key * 128 + swo, g_kh + gOff + ch * 8);
        CP_ASYNC16(bufBase + 8192 + key * 128 + swo, g_vh + gOff + ch * 8);
    }
}

__global__ __launch_bounds__(256, 2)
void attn_mma() {
    extern __shared__ __align__(1024) unsigned char sm[];
    const int tid = threadIdx.x;
    const int w   = tid >> 5;
    const int l   = tid & 31;
    const int c   = blockIdx.x;
    const uint32_t smBase = smem_u32(sm);

    const int u0 = (c * UNITS) / ATTN_GRID;
    const int u1 = ((c + 1) * UNITS) / ATTN_GRID;
    const int n  = u1 - u0;

    const int r = l & 7;
    const int rS = (l >> 4) * 8 + r;
    const int cS = (l >> 3) & 1;
    const int rV = ((l >> 3) & 1) * 8 + r;
    const int cV = l >> 4;
    const int qrow = w * 16 + (l & 7) + ((l >> 3) & 1) * 8;
    const int hi8  = l >> 4;

    const int qldRow = tid >> 1, qldSel = tid & 1;
    auto load_q = [&](int qb) {
        const size_t gOff = (size_t)(qb * QB + qldRow) * HD;
        char* dstRow = (char*)sm + qldRow * 128;
#pragma unroll
        for (int i = 0; i < 4; ++i) {
            const int ch = qldSel * 4 + i;
            uint4 val = *reinterpret_cast<const uint4*>(g_qh + gOff + ch * 8);
            *reinterpret_cast<uint4*>(dstRow + ((ch ^ (qldRow & 7)) << 4)) = val;
        }
    };

    uint32_t Qh[4][4];
    auto frag_q = [&]() {
#pragma unroll
        for (int kc = 0; kc < 4; ++kc) {
            const int cc = 2 * kc + hi8;
            ldsm4(Qh[kc], smBase + qrow * 128 + ((cc ^ (qrow & 7)) << 4));
        }
    };

    float O[8][4];
    float lacc0, lacc1;
    auto reset_acc = [&]() {
#pragma unroll
        for (int nn = 0; nn < 8; ++nn)
#pragma unroll
            for (int j = 0; j < 4; ++j) O[nn][j] = 0.f;
        lacc0 = 0.f; lacc1 = 0.f;
    };

    auto write_partial = [&](int qb, int slot) {
        const int row0 = qb * QB + w * 16 + (l >> 2);
        const int t    = l & 3;
        float* op = g_Opart[slot];
#pragma unroll
        for (int nn = 0; nn < 8; ++nn) {
            *reinterpret_cast<float2*>(op + (size_t)row0 * HD + 8 * nn + 2 * t) =
                make_float2(O[nn][0], O[nn][1]);
            *reinterpret_cast<float2*>(op + (size_t)(row0 + 8) * HD + 8 * nn + 2 * t) =
                make_float2(O[nn][2], O[nn][3]);
        }
        float s0 = lacc0, s1 = lacc1;
        s0 += __shfl_xor_sync(0xffffffffu, s0, 1);
        s0 += __shfl_xor_sync(0xffffffffu, s0, 2);
        s1 += __shfl_xor_sync(0xffffffffu, s1, 1);
        s1 += __shfl_xor_sync(0xffffffffu, s1, 2);
        if ((l & 3) == 0) {
            g_lpart[slot][row0]     = s0;
            g_lpart[slot][row0 + 8] = s1;
        }
    };

    // ---- prologue ----
    int cur_qb = u0 >> 7;
    load_q(cur_qb);
    issue_tile(smBase + 16384, (u0 & 127) * 64, tid);               CP_COMMIT();
    issue_tile(smBase + 32768, ((u0 + 1) & 127) * 64, tid);         CP_COMMIT();
    __syncthreads();
    frag_q();
    reset_acc();

    for (int u = u0; u < u1; ++u) {
        const int i = u - u0;
        CP_WAIT(1);
        __syncthreads();

        const int q_of_u = u >> 7;
        if (q_of_u != cur_qb) {
            const int slot = c - cta_of_unit(cur_qb << 7);
            write_partial(cur_qb, slot);
            cur_qb = q_of_u;
            load_q(cur_qb);
            __syncthreads();
            frag_q();
            reset_acc();
        }

        if (i + 2 < n)
            issue_tile(smBase + 16384 + ((i + 2) % 3) * 16384,
                       ((u + 2) & 127) * 64, tid);
        CP_COMMIT();

        const uint32_t uKH = smBase + 16384 + (i % 3) * 16384;
        const uint32_t uVH = uKH + 8192;

        float sd[2][2][4];
        {
            const int kk = rS;
#pragma unroll
            for (int j = 0; j < 4; ++j) { sd[0][0][j] = 0.f; sd[0][1][j] = 0.f; }
#pragma unroll
            for (int kc = 0; kc < 4; ++kc) {
                uint32_t kh[4];
                ldsm4(kh, uKH + kk * 128 + (((2 * kc + cS) ^ (kk & 7)) << 4));
                mma16816(sd[0][0], Qh[kc], kh[0], kh[1]);
                mma16816(sd[0][1], Qh[kc], kh[2], kh[3]);
            }
        }

#pragma unroll
        for (int np = 0; np < 4; ++np) {
            const int cur = np & 1, nxt = cur ^ 1;
            if (np < 3) {
                const int kk = 16 * (np + 1) + rS;
#pragma unroll
                for (int j = 0; j < 4; ++j) { sd[nxt][0][j] = 0.f; sd[nxt][1][j] = 0.f; }
#pragma unroll
                for (int kc = 0; kc < 4; ++kc) {
                    uint32_t kh[4];
                    ldsm4(kh, uKH + kk * 128 + (((2 * kc + cS) ^ (kk & 7)) << 4));
                    mma16816(sd[nxt][0], Qh[kc], kh[0], kh[1]);
                    mma16816(sd[nxt][1], Qh[kc], kh[2], kh[3]);
                }
            }
            uint32_t Ah[4];
            {
                float e0 = ex2f(sd[cur][0][0] * CEXP);
                float e1 = ex2f(sd[cur][0][1] * CEXP);
                float e2 = ex2f(sd[cur][0][2] * CEXP);
                float e3 = ex2f(sd[cur][0][3] * CEXP);
                float e4 = ex2f(sd[cur][1][0] * CEXP);
                float e5 = ex2f(sd[cur][1][1] * CEXP);
                float e6 = ex2f(sd[cur][1][2] * CEXP);
                float e7 = ex2f(sd[cur][1][3] * CEXP);
                lacc0 += (e0 + e1) + (e4 + e5);
                lacc1 += (e2 + e3) + (e6 + e7);
                Ah[0] = hpack(e0, e1); Ah[1] = hpack(e2, e3);
                Ah[2] = hpack(e4, e5); Ah[3] = hpack(e6, e7);
            }
            const int kkv = 16 * np + rV;
#pragma unroll
            for (int npo = 0; npo < 4; ++npo) {
                uint32_t vh[4];
                ldsm4t(vh, uVH + kkv * 128 + (((2 * npo + cV) ^ (kkv & 7)) << 4));
                mma16816(O[2*npo],   Ah, vh[0], vh[1]);
                mma16816(O[2*npo+1], Ah, vh[2], vh[3]);
            }
        }
    }

    {
        const int slot = c - cta_of_unit(cur_qb << 7);
        write_partial(cur_qb, slot);
    }
}

// ---------------------------------------------------------------------------
// Kernel 2: fused combine (NSLOT slots) + output GEMM, fp16 MMA (hi/lo 2-pass).
// Grid (64, 4): 128x128 per CTA, 256 threads (8 warps x 16 rows).
// Smem: Hhi@0 (16KB), Hlo@16384, W@32768 (16KB) = 48KB static.
// ---------------------------------------------------------------------------
__global__ __launch_bounds__(256) void out_gemm(float* __restrict__ out) {
    __shared__ __align__(1024) unsigned char sg[49152];
    __shared__ float sInv[128];

    const int tid = threadIdx.x;
    const int w   = tid >> 5;
    const int l   = tid & 31;
    const int mBase = blockIdx.x * 128;
    const int nBase = blockIdx.y * 128;
    const uint32_t sb = smem_u32(sg);

    {
        const int nrow = tid >> 1, sel = tid & 1;
        const __half* src = g_wht + (size_t)(nBase + nrow) * HD;
        const uint32_t dstRow = sb + 32768 + nrow * 128;
#pragma unroll
        for (int i = 0; i < 4; ++i) {
            const int ch = sel * 4 + i;
            CP_ASYNC16(dstRow + ((ch ^ (nrow & 7)) << 4), src + ch * 8);
        }
        CP_COMMIT();
    }

    const int row = tid >> 1, sel = tid & 1;
    float4 a4[8];
    {
        const size_t off = (size_t)(mBase + row) * HD + sel * 32;
#pragma unroll
        for (int i = 0; i < 8; ++i)
            a4[i] = reinterpret_cast<const float4*>(g_Opart[0] + off)[i];
#pragma unroll
        for (int s = 1; s < NSLOT; ++s) {
            const float4* os = reinterpret_cast<const float4*>(g_Opart[s] + off);
#pragma unroll
            for (int i = 0; i < 8; ++i) {
                float4 b = os[i];
                a4[i].x += b.x; a4[i].y += b.y; a4[i].z += b.z; a4[i].w += b.w;
            }
        }
    }
    if (tid < 128) {
        float ls = 0.f;
#pragma unroll
        for (int s = 0; s < NSLOT; ++s) ls += g_lpart[s][mBase + tid];
        sInv[tid] = 1.0f / ls;
    }
    __syncthreads();

    {
        const float inv = sInv[row];
        float fv[32];
#pragma unroll
        for (int i = 0; i < 8; ++i) {
            fv[4*i]   = a4[i].x * inv; fv[4*i+1] = a4[i].y * inv;
            fv[4*i+2] = a4[i].z * inv; fv[4*i+3] = a4[i].w * inv;
        }
        const uint32_t rowOff = row * 128;
#pragma unroll
        for (int g = 0; g < 4; ++g) {
            const int ch = sel * 4 + g;
            uint32_t hh[4], ll[4];
#pragma unroll
            for (int p = 0; p < 4; ++p)
                packpair(fv[8*g + 2*p], fv[8*g + 2*p + 1], hh[p], ll[p]);
            const uint32_t swo = ((ch ^ (row & 7)) << 4);
            *reinterpret_cast<uint4*>(sg + (rowOff + swo)) =
                make_uint4(hh[0], hh[1], hh[2], hh[3]);
            *reinterpret_cast<uint4*>(sg + (16384 + rowOff + swo)) =
                make_uint4(ll[0], ll[1], ll[2], ll[3]);
        }
    }
    CP_WAIT(0);
    __syncthreads();

    uint32_t Hh[4][4], Hl[4][4];
    {
        const int hrow = w * 16 + (l & 7) + ((l >> 3) & 1) * 8;
        const int hi8 = l >> 4;
#pragma unroll
        for (int kc = 0; kc < 4; ++kc) {
            const int cc = 2 * kc + hi8;
            const uint32_t addr = sb + hrow * 128 + ((cc ^ (hrow & 7)) << 4);
            ldsm4(Hh[kc], addr);
            ldsm4(Hl[kc], addr + 16384);
        }
    }

    float oD[16][4];
#pragma unroll
    for (int nn = 0; nn < 16; ++nn)
#pragma unroll
        for (int j = 0; j < 4; ++j) oD[nn][j] = 0.f;

    const int r = l & 7;
#pragma unroll
    for (int np = 0; np < 8; ++np) {
#pragma unroll
        for (int kc = 0; kc < 4; ++kc) {
            const int kk = 16 * np + (l >> 4) * 8 + r;
            const int cc = 2 * kc + ((l >> 3) & 1);
            uint32_t b[4];
            ldsm4(b, sb + 32768 + kk * 128 + ((cc ^ (kk & 7)) << 4));
            mma16816(oD[2*np],   Hh[kc], b[0], b[1]);
            mma16816(oD[2*np+1], Hh[kc], b[2], b[3]);
            mma16816(oD[2*np],   Hl[kc], b[0], b[1]);
            mma16816(oD[2*np+1], Hl[kc], b[2], b[3]);
        }
    }

    {
        const int row0 = mBase + w * 16 + (l >> 2);
        const int t    = l & 3;
#pragma unroll
        for (int nn = 0; nn < 16; ++nn) {
            const int col = nBase + 8 * nn + 2 * t;
            *reinterpret_cast<float2*>(out + (size_t)row0 * WW + col) =
                make_float2(oD[nn][0], oD[nn][1]);
            *reinterpret_cast<float2*>(out + (size_t)(row0 + 8) * WW + col) =
                make_float2(oD[nn][2], oD[nn][3]);
        }
    }
}

// ---------------------------------------------------------------------------
extern "C" void kernel_launch(void* const* d_in, const int* in_sizes, int n_in,
                              void* d_out, int out_size) {
    const float* q   = (const float*)d_in[0];
    const float* k   = (const float*)d_in[1];
    const float* v   = (const float*)d_in[2];
    const float* w_o = (const float*)d_in[3];
    float* out = (float*)d_out;

    cudaFuncSetAttribute(attn_mma, cudaFuncAttributeMaxDynamicSharedMemorySize, 65536);

    prologue_kernel<<<896, 256>>>(q, k, v, w_o);
    attn_mma<<<ATTN_GRID, 256, 65536>>>();
    out_gemm<<<dim3(S_LEN / 128, WW / 128), 256>>>(out);
}

// round 14
// speedup vs baseline: 1.0497x; 1.0497x over previous
#include <cuda_runtime.h>
#include <cuda_fp16.h>
#include <cstdint>

#define S_LEN 8192
#define HD 64
#define NHEADS 8
#define WW 512
#define QB 128
#define NQB (S_LEN/QB)            /* 64 */
#define UNITS 8192                /* 64 qb x 128 key-tiles */
#define ATTN_GRID 148
#define NSLOT 4
#define CEXP 0.1803368801111204f  /* 0.125 * log2(e) */

static __device__ float g_Opart[NSLOT][S_LEN * HD];   // zero-init; unused slots stay 0
static __device__ float g_lpart[NSLOT][S_LEN];
static __device__ __align__(16) __half g_qh[S_LEN * HD];
static __device__ __align__(16) __half g_kh[S_LEN * HD];
static __device__ __align__(16) __half g_vh[S_LEN * HD];
static __device__ __align__(16) __half g_wht[WW * HD];   // W_sum^T fp16 [n][k]

// ---------------- helpers ----------------
__device__ __forceinline__ uint32_t smem_u32(const void* p) {
    uint32_t a;
    asm("{ .reg .u64 t; cvta.to.shared.u64 t, %1; cvt.u32.u64 %0, t; }" : "=r"(a) : "l"(p));
    return a;
}
__device__ __forceinline__ void ldsm4(uint32_t* r, uint32_t a) {
    asm volatile("ldmatrix.sync.aligned.m8n8.x4.shared.b16 {%0,%1,%2,%3}, [%4];"
                 : "=r"(r[0]), "=r"(r[1]), "=r"(r[2]), "=r"(r[3]) : "r"(a));
}
__device__ __forceinline__ void ldsm4t(uint32_t* r, uint32_t a) {
    asm volatile("ldmatrix.sync.aligned.m8n8.x4.trans.shared.b16 {%0,%1,%2,%3}, [%4];"
                 : "=r"(r[0]), "=r"(r[1]), "=r"(r[2]), "=r"(r[3]) : "r"(a));
}
__device__ __forceinline__ void mma16816(float* d, const uint32_t* a, uint32_t b0, uint32_t b1) {
    asm volatile(
        "mma.sync.aligned.m16n8k16.row.col.f32.f16.f16.f32 "
        "{%0,%1,%2,%3}, {%4,%5,%6,%7}, {%8,%9}, {%0,%1,%2,%3};"
        : "+f"(d[0]), "+f"(d[1]), "+f"(d[2]), "+f"(d[3])
        : "r"(a[0]), "r"(a[1]), "r"(a[2]), "r"(a[3]), "r"(b0), "r"(b1));
}
__device__ __forceinline__ uint32_t hpack(float a, float b) {
    __half2 h = __floats2half2_rn(a, b);
    return *reinterpret_cast<uint32_t*>(&h);
}
__device__ __forceinline__ void packpair(float a, float b, uint32_t& hi, uint32_t& lo) {
    __half2 h = __floats2half2_rn(a, b);
    hi = *reinterpret_cast<uint32_t*>(&h);
    float fa = __half2float(h.x);
    float fb = __half2float(h.y);
    lo = hpack(a - fa, b - fb);
}
__device__ __forceinline__ float ex2f(float x) {
    float y; asm("ex2.approx.f32 %0, %1;" : "=f"(y) : "f"(x)); return y;
}
#define CP_ASYNC16(dst, src) \
    asm volatile("cp.async.cg.shared.global [%0], [%1], 16;" :: "r"(dst), "l"(src))
#define CP_COMMIT() asm volatile("cp.async.commit_group;" ::: "memory")
#define CP_WAIT(n)  asm volatile("cp.async.wait_group %0;" :: "n"(n) : "memory")

// first CTA whose range contains unit u
__device__ __forceinline__ int cta_of_unit(int u) {
    return (u * ATTN_GRID + ATTN_GRID - 1) / UNITS;
}

// ---------------------------------------------------------------------------
// Kernel 0 (merged prologue, R11-measured-best config):
// blocks 0..255 convert q/k/v (8 elems of each per thread);
// blocks 256..383 reduce w_o -> fp16 transposed W_sum.
// ---------------------------------------------------------------------------
__global__ void prologue_kernel(const float* __restrict__ q, const float* __restrict__ k,
                                const float* __restrict__ v, const float* __restrict__ w_o) {
    if (blockIdx.x < 256) {
        int t = blockIdx.x * blockDim.x + threadIdx.x;   // 0..65535
        int off = t * 8;
        const float* srcs[3] = {q, k, v};
        __half* dsts[3] = {g_qh, g_kh, g_vh};
#pragma unroll
        for (int a = 0; a < 3; ++a) {
            const float4* s = reinterpret_cast<const float4*>(srcs[a] + off);
            float4 x0 = s[0], x1 = s[1];
            reinterpret_cast<uint4*>(dsts[a] + off)[0] =
                make_uint4(hpack(x0.x, x0.y), hpack(x0.z, x0.w),
                           hpack(x1.x, x1.y), hpack(x1.z, x1.w));
        }
    } else {
        int idx = (blockIdx.x - 256) * blockDim.x + threadIdx.x;   // 0..32767
        int d = idx >> 9;
        int c = idx & 511;
        float s = 0.f;
#pragma unroll
        for (int h = 0; h < NHEADS; ++h)
            s += w_o[(h * HD + d) * WW + c];
        g_wht[c * HD + d] = __float2half(s);
    }
}

// ---------------------------------------------------------------------------
// Kernel 1: persistent flash attention over flat (qb, ktile) units.
// 148 CTAs x 256 threads (8 warps x 16 rows). cp.async triple-buffered KH/VH.
// S-loop kc-outer (accumulator reuse distance 8 to break HMMA RAW chains).
// Smem: Q@0 (16KB); buf b @ 16384 + b*16384: KH@0 VH@8192. Total 64KB.
// ---------------------------------------------------------------------------
__device__ __forceinline__ void issue_tile(uint32_t bufBase, int keyRow0, int tid) {
    const int key = tid >> 2, sub = tid & 3;
    const size_t gOff = (size_t)(keyRow0 + key) * HD;
#pragma unroll
    for (int i = 0; i < 2; ++i) {
        const int ch = sub * 2 + i;
        const uint32_t swo = ((ch ^ (key & 7)) << 4);
        CP_ASYNC16(bufBase + key * 128 + swo, g_kh + gOff + ch * 8);
        CP_ASYNC16(bufBase + 8192 + key * 128 + swo, g_vh + gOff + ch * 8);
    }
}

__global__ __launch_bounds__(256, 1)
void attn_mma() {
    extern __shared__ __align__(1024) unsigned char sm[];
    const int tid = threadIdx.x;
    const int w   = tid >> 5;
    const int l   = tid & 31;
    const int c   = blockIdx.x;
    const uint32_t smBase = smem_u32(sm);

    const int u0 = (c * UNITS) / ATTN_GRID;
    const int u1 = ((c + 1) * UNITS) / ATTN_GRID;
    const int n  = u1 - u0;

    const int r = l & 7;
    const int rS = (l >> 4) * 8 + r;
    const int cS = (l >> 3) & 1;
    const int rV = ((l >> 3) & 1) * 8 + r;
    const int cV = l >> 4;
    const int qrow = w * 16 + (l & 7) + ((l >> 3) & 1) * 8;
    const int hi8  = l >> 4;

    const int qldRow = tid >> 1, qldSel = tid & 1;
    auto load_q = [&](int qb) {
        const size_t gOff = (size_t)(qb * QB + qldRow) * HD;
        char* dstRow = (char*)sm + qldRow * 128;
#pragma unroll
        for (int i = 0; i < 4; ++i) {
            const int ch = qldSel * 4 + i;
            uint4 val = *reinterpret_cast<const uint4*>(g_qh + gOff + ch * 8);
            *reinterpret_cast<uint4*>(dstRow + ((ch ^ (qldRow & 7)) << 4)) = val;
        }
    };

    uint32_t Qh[4][4];
    auto frag_q = [&]() {
#pragma unroll
        for (int kc = 0; kc < 4; ++kc) {
            const int cc = 2 * kc + hi8;
            ldsm4(Qh[kc], smBase + qrow * 128 + ((cc ^ (qrow & 7)) << 4));
        }
    };

    float O[8][4];
    float lacc0, lacc1;
    auto reset_acc = [&]() {
#pragma unroll
        for (int nn = 0; nn < 8; ++nn)
#pragma unroll
            for (int j = 0; j < 4; ++j) O[nn][j] = 0.f;
        lacc0 = 0.f; lacc1 = 0.f;
    };

    auto write_partial = [&](int qb, int slot) {
        const int row0 = qb * QB + w * 16 + (l >> 2);
        const int t    = l & 3;
        float* op = g_Opart[slot];
#pragma unroll
        for (int nn = 0; nn < 8; ++nn) {
            *reinterpret_cast<float2*>(op + (size_t)row0 * HD + 8 * nn + 2 * t) =
                make_float2(O[nn][0], O[nn][1]);
            *reinterpret_cast<float2*>(op + (size_t)(row0 + 8) * HD + 8 * nn + 2 * t) =
                make_float2(O[nn][2], O[nn][3]);
        }
        float s0 = lacc0, s1 = lacc1;
        s0 += __shfl_xor_sync(0xffffffffu, s0, 1);
        s0 += __shfl_xor_sync(0xffffffffu, s0, 2);
        s1 += __shfl_xor_sync(0xffffffffu, s1, 1);
        s1 += __shfl_xor_sync(0xffffffffu, s1, 2);
        if ((l & 3) == 0) {
            g_lpart[slot][row0]     = s0;
            g_lpart[slot][row0 + 8] = s1;
        }
    };

    // ---- prologue ----
    int cur_qb = u0 >> 7;
    load_q(cur_qb);
    issue_tile(smBase + 16384, (u0 & 127) * 64, tid);               CP_COMMIT();
    issue_tile(smBase + 32768, ((u0 + 1) & 127) * 64, tid);         CP_COMMIT();
    __syncthreads();
    frag_q();
    reset_acc();

    for (int u = u0; u < u1; ++u) {
        const int i = u - u0;
        CP_WAIT(1);
        __syncthreads();

        const int q_of_u = u >> 7;
        if (q_of_u != cur_qb) {
            const int slot = c - cta_of_unit(cur_qb << 7);
            write_partial(cur_qb, slot);
            cur_qb = q_of_u;
            load_q(cur_qb);
            __syncthreads();
            frag_q();
            reset_acc();
        }

        if (i + 2 < n)
            issue_tile(smBase + 16384 + ((i + 2) % 3) * 16384,
                       ((u + 2) & 127) * 64, tid);
        CP_COMMIT();

        const uint32_t uKH = smBase + 16384 + (i % 3) * 16384;
        const uint32_t uVH = uKH + 8192;

        // ---- S = Q K^T : kc-outer, np-inner (RAW reuse distance = 8 MMAs) ----
        float sD[8][4];
#pragma unroll
        for (int nn = 0; nn < 8; ++nn)
#pragma unroll
            for (int j = 0; j < 4; ++j) sD[nn][j] = 0.f;

#pragma unroll
        for (int kc = 0; kc < 4; ++kc) {
            uint32_t kh[4][4];
#pragma unroll
            for (int np = 0; np < 4; ++np) {
                const int kk = 16 * np + rS;
                ldsm4(kh[np], uKH + kk * 128 + (((2 * kc + cS) ^ (kk & 7)) << 4));
            }
#pragma unroll
            for (int np = 0; np < 4; ++np) {
                mma16816(sD[2*np],   Qh[kc], kh[np][0], kh[np][1]);
                mma16816(sD[2*np+1], Qh[kc], kh[np][2], kh[np][3]);
            }
        }

        // ---- softmax: P = exp2(S * 0.125*log2e) ----
        uint32_t Ah[8][2];
#pragma unroll
        for (int nn = 0; nn < 8; ++nn) {
            float e0 = ex2f(sD[nn][0] * CEXP);
            float e1 = ex2f(sD[nn][1] * CEXP);
            float e2 = ex2f(sD[nn][2] * CEXP);
            float e3 = ex2f(sD[nn][3] * CEXP);
            lacc0 += e0 + e1;
            lacc1 += e2 + e3;
            Ah[nn][0] = hpack(e0, e1);
            Ah[nn][1] = hpack(e2, e3);
        }

        // ---- O += P V : kcv-outer, npo-inner (reuse distance 8) ----
#pragma unroll
        for (int kcv = 0; kcv < 4; ++kcv) {
            uint32_t A4[4] = {Ah[2*kcv][0], Ah[2*kcv][1], Ah[2*kcv+1][0], Ah[2*kcv+1][1]};
            const int kkv = 16 * kcv + rV;
#pragma unroll
            for (int npo = 0; npo < 4; ++npo) {
                uint32_t vh[4];
                ldsm4t(vh, uVH + kkv * 128 + (((2 * npo + cV) ^ (kkv & 7)) << 4));
                mma16816(O[2*npo],   A4, vh[0], vh[1]);
                mma16816(O[2*npo+1], A4, vh[2], vh[3]);
            }
        }
    }

    {
        const int slot = c - cta_of_unit(cur_qb << 7);
        write_partial(cur_qb, slot);
    }
}

// ---------------------------------------------------------------------------
// Kernel 2: fused combine (NSLOT slots) + output GEMM, fp16 MMA (hi/lo 2-pass).
// Grid (64, 4): 128x128 per CTA, 256 threads (8 warps x 16 rows).
// Smem: Hhi@0 (16KB), Hlo@16384, W@32768 (16KB) = 48KB static.
// ---------------------------------------------------------------------------
__global__ __launch_bounds__(256) void out_gemm(float* __restrict__ out) {
    __shared__ __align__(1024) unsigned char sg[49152];
    __shared__ float sInv[128];

    const int tid = threadIdx.x;
    const int w   = tid >> 5;
    const int l   = tid & 31;
    const int mBase = blockIdx.x * 128;
    const int nBase = blockIdx.y * 128;
    const uint32_t sb = smem_u32(sg);

    {
        const int nrow = tid >> 1, sel = tid & 1;
        const __half* src = g_wht + (size_t)(nBase + nrow) * HD;
        const uint32_t dstRow = sb + 32768 + nrow * 128;
#pragma unroll
        for (int i = 0; i < 4; ++i) {
            const int ch = sel * 4 + i;
            CP_ASYNC16(dstRow + ((ch ^ (nrow & 7)) << 4), src + ch * 8);
        }
        CP_COMMIT();
    }

    const int row = tid >> 1, sel = tid & 1;
    float4 a4[8];
    {
        const size_t off = (size_t)(mBase + row) * HD + sel * 32;
#pragma unroll
        for (int i = 0; i < 8; ++i)
            a4[i] = reinterpret_cast<const float4*>(g_Opart[0] + off)[i];
#pragma unroll
        for (int s = 1; s < NSLOT; ++s) {
            const float4* os = reinterpret_cast<const float4*>(g_Opart[s] + off);
#pragma unroll
            for (int i = 0; i < 8; ++i) {
                float4 b = os[i];
                a4[i].x += b.x; a4[i].y += b.y; a4[i].z += b.z; a4[i].w += b.w;
            }
        }
    }
    if (tid < 128) {
        float ls = 0.f;
#pragma unroll
        for (int s = 0; s < NSLOT; ++s) ls += g_lpart[s][mBase + tid];
        sInv[tid] = 1.0f / ls;
    }
    __syncthreads();

    {
        const float inv = sInv[row];
        float fv[32];
#pragma unroll
        for (int i = 0; i < 8; ++i) {
            fv[4*i]   = a4[i].x * inv; fv[4*i+1] = a4[i].y * inv;
            fv[4*i+2] = a4[i].z * inv; fv[4*i+3] = a4[i].w * inv;
        }
        const uint32_t rowOff = row * 128;
#pragma unroll
        for (int g = 0; g < 4; ++g) {
            const int ch = sel * 4 + g;
            uint32_t hh[4], ll[4];
#pragma unroll
            for (int p = 0; p < 4; ++p)
                packpair(fv[8*g + 2*p], fv[8*g + 2*p + 1], hh[p], ll[p]);
            const uint32_t swo = ((ch ^ (row & 7)) << 4);
            *reinterpret_cast<uint4*>(sg + (rowOff + swo)) =
                make_uint4(hh[0], hh[1], hh[2], hh[3]);
            *reinterpret_cast<uint4*>(sg + (16384 + rowOff + swo)) =
                make_uint4(ll[0], ll[1], ll[2], ll[3]);
        }
    }
    CP_WAIT(0);
    __syncthreads();

    uint32_t Hh[4][4], Hl[4][4];
    {
        const int hrow = w * 16 + (l & 7) + ((l >> 3) & 1) * 8;
        const int hi8 = l >> 4;
#pragma unroll
        for (int kc = 0; kc < 4; ++kc) {
            const int cc = 2 * kc + hi8;
            const uint32_t addr = sb + hrow * 128 + ((cc ^ (hrow & 7)) << 4);
            ldsm4(Hh[kc], addr);
            ldsm4(Hl[kc], addr + 16384);
        }
    }

    float oD[16][4];
#pragma unroll
    for (int nn = 0; nn < 16; ++nn)
#pragma unroll
        for (int j = 0; j < 4; ++j) oD[nn][j] = 0.f;

    const int r = l & 7;
#pragma unroll
    for (int np = 0; np < 8; ++np) {
#pragma unroll
        for (int kc = 0; kc < 4; ++kc) {
            const int kk = 16 * np + (l >> 4) * 8 + r;
            const int cc = 2 * kc + ((l >> 3) & 1);
            uint32_t b[4];
            ldsm4(b, sb + 32768 + kk * 128 + ((cc ^ (kk & 7)) << 4));
            mma16816(oD[2*np],   Hh[kc], b[0], b[1]);
            mma16816(oD[2*np+1], Hh[kc], b[2], b[3]);
            mma16816(oD[2*np],   Hl[kc], b[0], b[1]);
            mma16816(oD[2*np+1], Hl[kc], b[2], b[3]);
        }
    }

    {
        const int row0 = mBase + w * 16 + (l >> 2);
        const int t    = l & 3;
#pragma unroll
        for (int nn = 0; nn < 16; ++nn) {
            const int col = nBase + 8 * nn + 2 * t;
            *reinterpret_cast<float2*>(out + (size_t)row0 * WW + col) =
                make_float2(oD[nn][0], oD[nn][1]);
            *reinterpret_cast<float2*>(out + (size_t)(row0 + 8) * WW + col) =
                make_float2(oD[nn][2], oD[nn][3]);
        }
    }
}

// ---------------------------------------------------------------------------
extern "C" void kernel_launch(void* const* d_in, const int* in_sizes, int n_in,
                              void* d_out, int out_size) {
    const float* q   = (const float*)d_in[0];
    const float* k   = (const float*)d_in[1];
    const float* v   = (const float*)d_in[2];
    const float* w_o = (const float*)d_in[3];
    float* out = (float*)d_out;

    cudaFuncSetAttribute(attn_mma, cudaFuncAttributeMaxDynamicSharedMemorySize, 65536);

    prologue_kernel<<<384, 256>>>(q, k, v, w_o);
    attn_mma<<<ATTN_GRID, 256, 65536>>>();
    out_gemm<<<dim3(S_LEN / 128, WW / 128), 256>>>(out);
}

// round 15
// speedup vs baseline: 1.1135x; 1.0608x over previous
#include <cuda_runtime.h>
#include <cuda_fp16.h>
#include <cstdint>

#define S_LEN 8192
#define HD 64
#define NHEADS 8
#define WW 512
#define QB 256
#define NQB (S_LEN/QB)            /* 32 */
#define UNITS 4096                /* 32 qb x 128 key-tiles */
#define ATTN_GRID 148
#define NSLOT 6
#define CEXP 0.1803368801111204f  /* 0.125 * log2(e) */

static __device__ float g_Opart[NSLOT][S_LEN * HD];   // zero-init; unused slots stay 0
static __device__ float g_lpart[NSLOT][S_LEN];
static __device__ __align__(16) __half g_qh[S_LEN * HD];
static __device__ __align__(16) __half g_kh[S_LEN * HD];
static __device__ __align__(16) __half g_vh[S_LEN * HD];
static __device__ __align__(16) __half g_wht[WW * HD];   // W_sum^T fp16 [n][k]

// ---------------- helpers ----------------
__device__ __forceinline__ uint32_t smem_u32(const void* p) {
    uint32_t a;
    asm("{ .reg .u64 t; cvta.to.shared.u64 t, %1; cvt.u32.u64 %0, t; }" : "=r"(a) : "l"(p));
    return a;
}
__device__ __forceinline__ void ldsm4(uint32_t* r, uint32_t a) {
    asm volatile("ldmatrix.sync.aligned.m8n8.x4.shared.b16 {%0,%1,%2,%3}, [%4];"
                 : "=r"(r[0]), "=r"(r[1]), "=r"(r[2]), "=r"(r[3]) : "r"(a));
}
__device__ __forceinline__ void ldsm4t(uint32_t* r, uint32_t a) {
    asm volatile("ldmatrix.sync.aligned.m8n8.x4.trans.shared.b16 {%0,%1,%2,%3}, [%4];"
                 : "=r"(r[0]), "=r"(r[1]), "=r"(r[2]), "=r"(r[3]) : "r"(a));
}
__device__ __forceinline__ void mma16816(float* d, const uint32_t* a, uint32_t b0, uint32_t b1) {
    asm volatile(
        "mma.sync.aligned.m16n8k16.row.col.f32.f16.f16.f32 "
        "{%0,%1,%2,%3}, {%4,%5,%6,%7}, {%8,%9}, {%0,%1,%2,%3};"
        : "+f"(d[0]), "+f"(d[1]), "+f"(d[2]), "+f"(d[3])
        : "r"(a[0]), "r"(a[1]), "r"(a[2]), "r"(a[3]), "r"(b0), "r"(b1));
}
__device__ __forceinline__ uint32_t hpack(float a, float b) {
    __half2 h = __floats2half2_rn(a, b);
    return *reinterpret_cast<uint32_t*>(&h);
}
__device__ __forceinline__ void packpair(float a, float b, uint32_t& hi, uint32_t& lo) {
    __half2 h = __floats2half2_rn(a, b);
    hi = *reinterpret_cast<uint32_t*>(&h);
    float fa = __half2float(h.x);
    float fb = __half2float(h.y);
    lo = hpack(a - fa, b - fb);
}
__device__ __forceinline__ float ex2f(float x) {
    float y; asm("ex2.approx.f32 %0, %1;" : "=f"(y) : "f"(x)); return y;
}
#define CP_ASYNC16(dst, src) \
    asm volatile("cp.async.cg.shared.global [%0], [%1], 16;" :: "r"(dst), "l"(src))
#define CP_COMMIT() asm volatile("cp.async.commit_group;" ::: "memory")
#define CP_WAIT(n)  asm volatile("cp.async.wait_group %0;" :: "n"(n) : "memory")

// first CTA whose range contains unit u
__device__ __forceinline__ int cta_of_unit(int u) {
    return (u * ATTN_GRID + ATTN_GRID - 1) / UNITS;
}

// ---------------------------------------------------------------------------
// Kernel 0 (merged prologue): blocks 0..255 convert q/k/v (8 elems each);
// blocks 256..383 reduce w_o -> fp16 transposed W_sum.
// ---------------------------------------------------------------------------
__global__ void prologue_kernel(const float* __restrict__ q, const float* __restrict__ k,
                                const float* __restrict__ v, const float* __restrict__ w_o) {
    if (blockIdx.x < 256) {
        int t = blockIdx.x * blockDim.x + threadIdx.x;   // 0..65535
        int off = t * 8;
        const float* srcs[3] = {q, k, v};
        __half* dsts[3] = {g_qh, g_kh, g_vh};
#pragma unroll
        for (int a = 0; a < 3; ++a) {
            const float4* s = reinterpret_cast<const float4*>(srcs[a] + off);
            float4 x0 = s[0], x1 = s[1];
            reinterpret_cast<uint4*>(dsts[a] + off)[0] =
                make_uint4(hpack(x0.x, x0.y), hpack(x0.z, x0.w),
                           hpack(x1.x, x1.y), hpack(x1.z, x1.w));
        }
    } else {
        int idx = (blockIdx.x - 256) * blockDim.x + threadIdx.x;   // 0..32767
        int d = idx >> 9;
        int c = idx & 511;
        float s = 0.f;
#pragma unroll
        for (int h = 0; h < NHEADS; ++h)
            s += w_o[(h * HD + d) * WW + c];
        g_wht[c * HD + d] = __float2half(s);
    }
}

// ---------------------------------------------------------------------------
// Kernel 1: persistent flash attention, QB=256 (2 M-frags/warp).
// 148 CTAs x 256 threads. cp.async triple-buffered KH/VH (64-key tiles).
// Smem: Q@0 (32KB); buf b @ 32768 + b*16384: KH@0 VH@8192. Total 80KB.
// ---------------------------------------------------------------------------
__device__ __forceinline__ void issue_tile(uint32_t bufBase, int keyRow0, int tid) {
    const int key = tid >> 2, sub = tid & 3;
    const size_t gOff = (size_t)(keyRow0 + key) * HD;
#pragma unroll
    for (int i = 0; i < 2; ++i) {
        const int ch = sub * 2 + i;
        const uint32_t swo = ((ch ^ (key & 7)) << 4);
        CP_ASYNC16(bufBase + key * 128 + swo, g_kh + gOff + ch * 8);
        CP_ASYNC16(bufBase + 8192 + key * 128 + swo, g_vh + gOff + ch * 8);
    }
}

__global__ __launch_bounds__(256, 1)
void attn_mma() {
    extern __shared__ __align__(1024) unsigned char sm[];
    const int tid = threadIdx.x;
    const int w   = tid >> 5;
    const int l   = tid & 31;
    const int c   = blockIdx.x;
    const uint32_t smBase = smem_u32(sm);

    const int u0 = (c * UNITS) / ATTN_GRID;
    const int u1 = ((c + 1) * UNITS) / ATTN_GRID;
    const int n  = u1 - u0;

    const int r = l & 7;
    const int rS = (l >> 4) * 8 + r;
    const int cS = (l >> 3) & 1;
    const int rV = ((l >> 3) & 1) * 8 + r;
    const int cV = l >> 4;
    const int hi8  = l >> 4;

    // ---- Q loader: 256 threads, 1 row each (128B via 8 uint4) ----
    auto load_q = [&](int qb) {
        const size_t gOff = (size_t)(qb * QB + tid) * HD;
        char* dstRow = (char*)sm + tid * 128;
#pragma unroll
        for (int ch = 0; ch < 8; ++ch) {
            uint4 val = *reinterpret_cast<const uint4*>(g_qh + gOff + ch * 8);
            *reinterpret_cast<uint4*>(dstRow + ((ch ^ (tid & 7)) << 4)) = val;
        }
    };

    uint32_t Qh[2][4][4];
    auto frag_q = [&]() {
#pragma unroll
        for (int f = 0; f < 2; ++f) {
            const int qrow = w * 32 + f * 16 + (l & 7) + ((l >> 3) & 1) * 8;
#pragma unroll
            for (int kc = 0; kc < 4; ++kc) {
                const int cc = 2 * kc + hi8;
                ldsm4(Qh[f][kc], smBase + qrow * 128 + ((cc ^ (qrow & 7)) << 4));
            }
        }
    };

    float O[2][8][4];
    float lacc[2][2];
    auto reset_acc = [&]() {
#pragma unroll
        for (int f = 0; f < 2; ++f) {
#pragma unroll
            for (int nn = 0; nn < 8; ++nn)
#pragma unroll
                for (int j = 0; j < 4; ++j) O[f][nn][j] = 0.f;
            lacc[f][0] = 0.f; lacc[f][1] = 0.f;
        }
    };

    auto write_partial = [&](int qb, int slot) {
        float* op = g_Opart[slot];
        const int t = l & 3;
#pragma unroll
        for (int f = 0; f < 2; ++f) {
            const int row0 = qb * QB + w * 32 + f * 16 + (l >> 2);
#pragma unroll
            for (int nn = 0; nn < 8; ++nn) {
                *reinterpret_cast<float2*>(op + (size_t)row0 * HD + 8 * nn + 2 * t) =
                    make_float2(O[f][nn][0], O[f][nn][1]);
                *reinterpret_cast<float2*>(op + (size_t)(row0 + 8) * HD + 8 * nn + 2 * t) =
                    make_float2(O[f][nn][2], O[f][nn][3]);
            }
            float s0 = lacc[f][0], s1 = lacc[f][1];
            s0 += __shfl_xor_sync(0xffffffffu, s0, 1);
            s0 += __shfl_xor_sync(0xffffffffu, s0, 2);
            s1 += __shfl_xor_sync(0xffffffffu, s1, 1);
            s1 += __shfl_xor_sync(0xffffffffu, s1, 2);
            if ((l & 3) == 0) {
                g_lpart[slot][row0]     = s0;
                g_lpart[slot][row0 + 8] = s1;
            }
        }
    };

    // ---- prologue ----
    int cur_qb = u0 >> 7;
    load_q(cur_qb);
    issue_tile(smBase + 32768, (u0 & 127) * 64, tid);                       CP_COMMIT();
    issue_tile(smBase + 32768 + 16384, ((u0 + 1) & 127) * 64, tid);         CP_COMMIT();
    __syncthreads();
    frag_q();
    reset_acc();

    for (int u = u0; u < u1; ++u) {
        const int i = u - u0;
        CP_WAIT(1);
        __syncthreads();

        const int q_of_u = u >> 7;
        if (q_of_u != cur_qb) {
            const int slot = c - cta_of_unit(cur_qb << 7);
            write_partial(cur_qb, slot);
            cur_qb = q_of_u;
            load_q(cur_qb);
            __syncthreads();
            frag_q();
            reset_acc();
        }

        if (i + 2 < n)
            issue_tile(smBase + 32768 + ((i + 2) % 3) * 16384,
                       ((u + 2) & 127) * 64, tid);
        CP_COMMIT();

        const uint32_t uKH = smBase + 32768 + (i % 3) * 16384;
        const uint32_t uVH = uKH + 8192;

        // ---- S = Q K^T : kc-outer; K frags shared by both M-frags ----
        float sD[2][8][4];
#pragma unroll
        for (int f = 0; f < 2; ++f)
#pragma unroll
            for (int nn = 0; nn < 8; ++nn)
#pragma unroll
                for (int j = 0; j < 4; ++j) sD[f][nn][j] = 0.f;

#pragma unroll
        for (int kc = 0; kc < 4; ++kc) {
            uint32_t kh[4][4];
#pragma unroll
            for (int np = 0; np < 4; ++np) {
                const int kk = 16 * np + rS;
                ldsm4(kh[np], uKH + kk * 128 + (((2 * kc + cS) ^ (kk & 7)) << 4));
            }
#pragma unroll
            for (int np = 0; np < 4; ++np) {
#pragma unroll
                for (int f = 0; f < 2; ++f) {
                    mma16816(sD[f][2*np],   Qh[f][kc], kh[np][0], kh[np][1]);
                    mma16816(sD[f][2*np+1], Qh[f][kc], kh[np][2], kh[np][3]);
                }
            }
        }

        // ---- exp + PV per kcv chunk; V frags shared by both M-frags ----
#pragma unroll
        for (int kcv = 0; kcv < 4; ++kcv) {
            uint32_t vh[4][4];
            const int kkv = 16 * kcv + rV;
#pragma unroll
            for (int npo = 0; npo < 4; ++npo)
                ldsm4t(vh[npo], uVH + kkv * 128 + (((2 * npo + cV) ^ (kkv & 7)) << 4));
#pragma unroll
            for (int f = 0; f < 2; ++f) {
                float e0 = ex2f(sD[f][2*kcv][0] * CEXP);
                float e1 = ex2f(sD[f][2*kcv][1] * CEXP);
                float e2 = ex2f(sD[f][2*kcv][2] * CEXP);
                float e3 = ex2f(sD[f][2*kcv][3] * CEXP);
                float e4 = ex2f(sD[f][2*kcv+1][0] * CEXP);
                float e5 = ex2f(sD[f][2*kcv+1][1] * CEXP);
                float e6 = ex2f(sD[f][2*kcv+1][2] * CEXP);
                float e7 = ex2f(sD[f][2*kcv+1][3] * CEXP);
                lacc[f][0] += (e0 + e1) + (e4 + e5);
                lacc[f][1] += (e2 + e3) + (e6 + e7);
                uint32_t A4[4] = {hpack(e0, e1), hpack(e2, e3),
                                  hpack(e4, e5), hpack(e6, e7)};
#pragma unroll
                for (int npo = 0; npo < 4; ++npo) {
                    mma16816(O[f][2*npo],   A4, vh[npo][0], vh[npo][1]);
                    mma16816(O[f][2*npo+1], A4, vh[npo][2], vh[npo][3]);
                }
            }
        }
    }

    {
        const int slot = c - cta_of_unit(cur_qb << 7);
        write_partial(cur_qb, slot);
    }
}

// ---------------------------------------------------------------------------
// Kernel 2: fused combine (NSLOT slots) + output GEMM, fp16 MMA (hi/lo 2-pass).
// Grid (64, 4): 128x128 per CTA, 256 threads (8 warps x 16 rows).
// Smem: Hhi@0 (16KB), Hlo@16384, W@32768 (16KB) = 48KB static.
// ---------------------------------------------------------------------------
__global__ __launch_bounds__(256) void out_gemm(float* __restrict__ out) {
    __shared__ __align__(1024) unsigned char sg[49152];
    __shared__ float sInv[128];

    const int tid = threadIdx.x;
    const int w   = tid >> 5;
    const int l   = tid & 31;
    const int mBase = blockIdx.x * 128;
    const int nBase = blockIdx.y * 128;
    const uint32_t sb = smem_u32(sg);

    {
        const int nrow = tid >> 1, sel = tid & 1;
        const __half* src = g_wht + (size_t)(nBase + nrow) * HD;
        const uint32_t dstRow = sb + 32768 + nrow * 128;
#pragma unroll
        for (int i = 0; i < 4; ++i) {
            const int ch = sel * 4 + i;
            CP_ASYNC16(dstRow + ((ch ^ (nrow & 7)) << 4), src + ch * 8);
        }
        CP_COMMIT();
    }

    const int row = tid >> 1, sel = tid & 1;
    float4 a4[8];
    {
        const size_t off = (size_t)(mBase + row) * HD + sel * 32;
#pragma unroll
        for (int i = 0; i < 8; ++i)
            a4[i] = reinterpret_cast<const float4*>(g_Opart[0] + off)[i];
#pragma unroll
        for (int s = 1; s < NSLOT; ++s) {
            const float4* os = reinterpret_cast<const float4*>(g_Opart[s] + off);
#pragma unroll
            for (int i = 0; i < 8; ++i) {
                float4 b = os[i];
                a4[i].x += b.x; a4[i].y += b.y; a4[i].z += b.z; a4[i].w += b.w;
            }
        }
    }
    if (tid < 128) {
        float ls = 0.f;
#pragma unroll
        for (int s = 0; s < NSLOT; ++s) ls += g_lpart[s][mBase + tid];
        sInv[tid] = 1.0f / ls;
    }
    __syncthreads();

    {
        const float inv = sInv[row];
        float fv[32];
#pragma unroll
        for (int i = 0; i < 8; ++i) {
            fv[4*i]   = a4[i].x * inv; fv[4*i+1] = a4[i].y * inv;
            fv[4*i+2] = a4[i].z * inv; fv[4*i+3] = a4[i].w * inv;
        }
        const uint32_t rowOff = row * 128;
#pragma unroll
        for (int g = 0; g < 4; ++g) {
            const int ch = sel * 4 + g;
            uint32_t hh[4], ll[4];
#pragma unroll
            for (int p = 0; p < 4; ++p)
                packpair(fv[8*g + 2*p], fv[8*g + 2*p + 1], hh[p], ll[p]);
            const uint32_t swo = ((ch ^ (row & 7)) << 4);
            *reinterpret_cast<uint4*>(sg + (rowOff + swo)) =
                make_uint4(hh[0], hh[1], hh[2], hh[3]);
            *reinterpret_cast<uint4*>(sg + (16384 + rowOff + swo)) =
                make_uint4(ll[0], ll[1], ll[2], ll[3]);
        }
    }
    CP_WAIT(0);
    __syncthreads();

    uint32_t Hh[4][4], Hl[4][4];
    {
        const int hrow = w * 16 + (l & 7) + ((l >> 3) & 1) * 8;
        const int hi8 = l >> 4;
#pragma unroll
        for (int kc = 0; kc < 4; ++kc) {
            const int cc = 2 * kc + hi8;
            const uint32_t addr = sb + hrow * 128 + ((cc ^ (hrow & 7)) << 4);
            ldsm4(Hh[kc], addr);
            ldsm4(Hl[kc], addr + 16384);
        }
    }

    float oD[16][4];
#pragma unroll
    for (int nn = 0; nn < 16; ++nn)
#pragma unroll
        for (int j = 0; j < 4; ++j) oD[nn][j] = 0.f;

    const int r = l & 7;
#pragma unroll
    for (int np = 0; np < 8; ++np) {
#pragma unroll
        for (int kc = 0; kc < 4; ++kc) {
            const int kk = 16 * np + (l >> 4) * 8 + r;
            const int cc = 2 * kc + ((l >> 3) & 1);
            uint32_t b[4];
            ldsm4(b, sb + 32768 + kk * 128 + ((cc ^ (kk & 7)) << 4));
            mma16816(oD[2*np],   Hh[kc], b[0], b[1]);
            mma16816(oD[2*np+1], Hh[kc], b[2], b[3]);
            mma16816(oD[2*np],   Hl[kc], b[0], b[1]);
            mma16816(oD[2*np+1], Hl[kc], b[2], b[3]);
        }
    }

    {
        const int row0 = mBase + w * 16 + (l >> 2);
        const int t    = l & 3;
#pragma unroll
        for (int nn = 0; nn < 16; ++nn) {
            const int col = nBase + 8 * nn + 2 * t;
            *reinterpret_cast<float2*>(out + (size_t)row0 * WW + col) =
                make_float2(oD[nn][0], oD[nn][1]);
            *reinterpret_cast<float2*>(out + (size_t)(row0 + 8) * WW + col) =
                make_float2(oD[nn][2], oD[nn][3]);
        }
    }
}

// ---------------------------------------------------------------------------
extern "C" void kernel_launch(void* const* d_in, const int* in_sizes, int n_in,
                              void* d_out, int out_size) {
    const float* q   = (const float*)d_in[0];
    const float* k   = (const float*)d_in[1];
    const float* v   = (const float*)d_in[2];
    const float* w_o = (const float*)d_in[3];
    float* out = (float*)d_out;

    cudaFuncSetAttribute(attn_mma, cudaFuncAttributeMaxDynamicSharedMemorySize, 81920);

    prologue_kernel<<<384, 256>>>(q, k, v, w_o);
    attn_mma<<<ATTN_GRID, 256, 81920>>>();
    out_gemm<<<dim3(S_LEN / 128, WW / 128), 256>>>(out);
}